// round 2
// baseline (speedup 1.0000x reference)
#include <cuda_runtime.h>
#include <stdint.h>

// Problem constants (shapes fixed by the dataset)
#define NMAX 100000
#define F    128

// Scratch (allocation-free rule: __device__ globals)
__device__ float g_xw  [NMAX * F];  // x @ W1
__device__ float g_acc1[NMAX * F];  // layer-1 aggregation accumulator (incl. self-loop + b1)
__device__ float g_hw  [NMAX * F];  // relu(h1) @ W2
__device__ float g_deg [NMAX];
__device__ float g_dinv[NMAX];

// ---------------------------------------------------------------------------
// Degree / normalization
// ---------------------------------------------------------------------------
__global__ void k_deg_init(int N) {
    int i = blockIdx.x * blockDim.x + threadIdx.x;
    if (i < N) g_deg[i] = 1.0f;  // self-loop
}

__global__ void k_deg_count(const int* __restrict__ ei, int E) {
    int e = blockIdx.x * blockDim.x + threadIdx.x;
    if (e < E) {
        int c = ei[E + e];  // col = edge_index[1]
        atomicAdd(&g_deg[c], 1.0f);
    }
}

__global__ void k_dinv(int N) {
    int i = blockIdx.x * blockDim.x + threadIdx.x;
    if (i < N) g_dinv[i] = rsqrtf(g_deg[i]);
}

// ---------------------------------------------------------------------------
// SGEMM: out[M,128] = A[M,128] @ W[128,128]
//   RELU_A: apply relu to A elements on load (fuses layer-1 activation)
//   Epilogue writes BOTH the raw product (outP) and the aggregation accumulator
//   initialized with the self-loop message + bias: outAcc = prod*dinv[r]^2 + bias
// BM=128, BN=128(full), BK=8, 256 threads, 8x8 register micro-tile.
// ---------------------------------------------------------------------------
template <bool RELU_A>
__global__ void __launch_bounds__(256, 2)
k_gemm128(const float* __restrict__ A, const float* __restrict__ W,
          const float* __restrict__ bias,
          float* __restrict__ outP, float* __restrict__ outAcc, int M)
{
    __shared__ float As[8][128];
    __shared__ float Bs[8][128];

    const int tid = threadIdx.x;
    const int tx  = tid & 15;    // 0..15 -> col groups of 8
    const int ty  = tid >> 4;    // 0..15 -> row groups of 8
    const int block_row = blockIdx.x * 128;

    float acc[8][8];
#pragma unroll
    for (int i = 0; i < 8; i++)
#pragma unroll
        for (int j = 0; j < 8; j++) acc[i][j] = 0.0f;

    // A-tile load mapping: thread -> (row = tid/2, k-seg = (tid&1)*4)
    const int ar = tid >> 1;
    const int ac = (tid & 1) * 4;
    // W-tile load mapping: thread -> (k-row = tid/32, col = (tid&31)*4)
    const int kr = tid >> 5;
    const int nc = (tid & 31) * 4;

    for (int k0 = 0; k0 < 128; k0 += 8) {
        int grow = block_row + ar;
        float4 av;
        if (grow < M) {
            av = *(const float4*)(A + (size_t)grow * F + k0 + ac);
        } else {
            av = make_float4(0.f, 0.f, 0.f, 0.f);
        }
        if (RELU_A) {
            av.x = fmaxf(av.x, 0.f); av.y = fmaxf(av.y, 0.f);
            av.z = fmaxf(av.z, 0.f); av.w = fmaxf(av.w, 0.f);
        }
        As[ac + 0][ar] = av.x;
        As[ac + 1][ar] = av.y;
        As[ac + 2][ar] = av.z;
        As[ac + 3][ar] = av.w;

        *(float4*)&Bs[kr][nc] = *(const float4*)(W + (size_t)(k0 + kr) * F + nc);

        __syncthreads();

#pragma unroll
        for (int k = 0; k < 8; k++) {
            float a[8], b[8];
            *(float4*)&a[0] = *(float4*)&As[k][ty * 8];
            *(float4*)&a[4] = *(float4*)&As[k][ty * 8 + 4];
            *(float4*)&b[0] = *(float4*)&Bs[k][tx * 8];
            *(float4*)&b[4] = *(float4*)&Bs[k][tx * 8 + 4];
#pragma unroll
            for (int i = 0; i < 8; i++)
#pragma unroll
                for (int j = 0; j < 8; j++)
                    acc[i][j] = fmaf(a[i], b[j], acc[i][j]);
        }
        __syncthreads();
    }

    // Epilogue: write product + initialize aggregation accumulator
#pragma unroll
    for (int i = 0; i < 8; i++) {
        int r = block_row + ty * 8 + i;
        if (r >= M) break;
        float di = g_dinv[r];
        float s  = di * di;  // self-loop norm
#pragma unroll
        for (int j = 0; j < 8; j += 4) {
            int c = tx * 8 + j;
            float4 v = make_float4(acc[i][j], acc[i][j + 1], acc[i][j + 2], acc[i][j + 3]);
            *(float4*)(outP + (size_t)r * F + c) = v;
            float4 bb = *(const float4*)(bias + c);
            float4 w = make_float4(fmaf(v.x, s, bb.x), fmaf(v.y, s, bb.y),
                                   fmaf(v.z, s, bb.z), fmaf(v.w, s, bb.w));
            *(float4*)(outAcc + (size_t)r * F + c) = w;
        }
    }
}

// ---------------------------------------------------------------------------
// Edge aggregation: one warp per edge.
//   acc[col] += xw[row] * (dinv[row]*dinv[col])
// 128 floats per edge -> 32 lanes x float4; vector red.global.add.v4.f32.
// ---------------------------------------------------------------------------
__global__ void __launch_bounds__(256)
k_edge_agg(const float* __restrict__ src, const int* __restrict__ ei,
           float* __restrict__ acc, int E)
{
    int e = blockIdx.x * (blockDim.x >> 5) + (threadIdx.x >> 5);
    if (e >= E) return;
    int lane = threadIdx.x & 31;

    int r = __ldg(ei + e);
    int c = __ldg(ei + E + e);
    float norm = g_dinv[r] * g_dinv[c];

    float4 v = __ldg((const float4*)(src + (size_t)r * F) + lane);
    v.x *= norm; v.y *= norm; v.z *= norm; v.w *= norm;

    float* dst = acc + (size_t)c * F + lane * 4;
    asm volatile("red.global.add.v4.f32 [%0], {%1, %2, %3, %4};"
                 :: "l"(dst), "f"(v.x), "f"(v.y), "f"(v.z), "f"(v.w)
                 : "memory");
}

// ---------------------------------------------------------------------------
// Launch
// ---------------------------------------------------------------------------
extern "C" void kernel_launch(void* const* d_in, const int* in_sizes, int n_in,
                              void* d_out, int out_size)
{
    const float* x  = (const float*)d_in[0];
    const int*   ei = (const int*)d_in[1];
    const float* W1 = (const float*)d_in[2];
    const float* b1 = (const float*)d_in[3];
    const float* W2 = (const float*)d_in[4];
    const float* b2 = (const float*)d_in[5];
    float*       out = (float*)d_out;

    const int N = in_sizes[0] / F;       // 100000
    const int E = in_sizes[1] / 2;       // 640000

    float* xw;   cudaGetSymbolAddress((void**)&xw,   g_xw);
    float* acc1; cudaGetSymbolAddress((void**)&acc1, g_acc1);
    float* hw;   cudaGetSymbolAddress((void**)&hw,   g_hw);

    const int T = 256;

    // Degree / normalization
    k_deg_init <<<(N + T - 1) / T, T>>>(N);
    k_deg_count<<<(E + T - 1) / T, T>>>(ei, E);
    k_dinv     <<<(N + T - 1) / T, T>>>(N);

    const int gemm_blocks = (N + 127) / 128;
    const int edge_blocks = (E + 7) / 8;   // 8 warps (edges) per 256-thread block

    // Layer 1: xw = x@W1 ; acc1 = xw*dinv^2 + b1 ; acc1 += messages
    k_gemm128<false><<<gemm_blocks, T>>>(x, W1, b1, xw, acc1, N);
    k_edge_agg<<<edge_blocks, T>>>(xw, ei, acc1, E);

    // Layer 2: hw = relu(acc1)@W2 ; out = hw*dinv^2 + b2 ; out += messages
    k_gemm128<true><<<gemm_blocks, T>>>(acc1, W2, b2, hw, out, N);
    k_edge_agg<<<edge_blocks, T>>>(hw, ei, out, E);
}

// round 4
// speedup vs baseline: 1.4958x; 1.4958x over previous
#include <cuda_runtime.h>
#include <cuda_bf16.h>
#include <stdint.h>

#define NMAX 100000
#define F    128

// Scratch (allocation-free rule: __device__ globals)
__device__ float g_xw  [NMAX * F];
__device__ float g_acc1[NMAX * F];
__device__ float g_hw  [NMAX * F];
__device__ float g_deg [NMAX];
__device__ float g_dinv[NMAX];
// W in mma B-fragment layout: [layer][hl][ktile(8)][warp_n(4)][lane(32)][8 u32]
// u32 = two bf16 (k, k+1) for B fragment of m16n8k16 col-major.
__device__ uint32_t g_wfrag[2][2][8][4][32][8];

// ---------------------------------------------------------------------------
// Helpers
// ---------------------------------------------------------------------------
__device__ __forceinline__ uint32_t smem_u32(const void* p) {
    uint32_t a;
    asm("{ .reg .u64 t; cvta.to.shared.u64 t, %1; cvt.u32.u64 %0, t; }" : "=r"(a) : "l"(p));
    return a;
}
__device__ __forceinline__ uint32_t pack_hi(float a, float b) {
    __nv_bfloat16 x = __float2bfloat16_rn(a), y = __float2bfloat16_rn(b);
    return (uint32_t)*(unsigned short*)&x | ((uint32_t)*(unsigned short*)&y << 16);
}
__device__ __forceinline__ uint32_t pack_lo(float a, float b) {
    __nv_bfloat16 x = __float2bfloat16_rn(a), y = __float2bfloat16_rn(b);
    float ra = a - __bfloat162float(x), rb = b - __bfloat162float(y);
    __nv_bfloat16 lx = __float2bfloat16_rn(ra), ly = __float2bfloat16_rn(rb);
    return (uint32_t)*(unsigned short*)&lx | ((uint32_t)*(unsigned short*)&ly << 16);
}
__device__ __forceinline__ void mma_bf16(float* d, const uint32_t* a, uint32_t b0, uint32_t b1) {
    asm volatile(
        "mma.sync.aligned.m16n8k16.row.col.f32.bf16.bf16.f32 "
        "{%0,%1,%2,%3}, {%4,%5,%6,%7}, {%8,%9}, {%0,%1,%2,%3};"
        : "+f"(d[0]), "+f"(d[1]), "+f"(d[2]), "+f"(d[3])
        : "r"(a[0]), "r"(a[1]), "r"(a[2]), "r"(a[3]), "r"(b0), "r"(b1));
}
__device__ __forceinline__ void ldsm4(uint32_t* r, uint32_t addr) {
    asm volatile("ldmatrix.sync.aligned.m8n8.x4.shared.b16 {%0,%1,%2,%3}, [%4];"
                 : "=r"(r[0]), "=r"(r[1]), "=r"(r[2]), "=r"(r[3]) : "r"(addr));
}

// ---------------------------------------------------------------------------
// Degree / normalization
// ---------------------------------------------------------------------------
__global__ void k_deg_init(int N) {
    int i = blockIdx.x * blockDim.x + threadIdx.x;
    if (i < N) g_deg[i] = 1.0f;
}
__global__ void k_deg_count(const int* __restrict__ ei, int E) {
    int e = blockIdx.x * blockDim.x + threadIdx.x;
    if (e < E) atomicAdd(&g_deg[ei[E + e]], 1.0f);
}
__global__ void k_dinv(int N) {
    int i = blockIdx.x * blockDim.x + threadIdx.x;
    if (i < N) g_dinv[i] = rsqrtf(g_deg[i]);
}

// ---------------------------------------------------------------------------
// W split into mma B-fragment layout (hi/lo bf16).
// Fragment (m16n8k16, col-major B): reg r of lane l in tile (kt, nt):
//   n = nt*8 + l/4 ; k = kt*16 + (l%4)*2 + r*8 ; value = {W[k][n], W[k+1][n]}
// nt = wn*4 + j ; storage index [hl][kt][wn][lane][j*2+r]
// ---------------------------------------------------------------------------
__global__ void k_wsplit(const float* __restrict__ W, int layer) {
    int id = blockIdx.x * blockDim.x + threadIdx.x;
    if (id >= 16384) return;
    int jr   = id & 7;
    int lane = (id >> 3) & 31;
    int wn   = (id >> 8) & 3;
    int kt   = (id >> 10) & 7;
    int hl   = id >> 13;
    int j = jr >> 1, r = jr & 1;
    int n = (wn * 4 + j) * 8 + (lane >> 2);
    int k = kt * 16 + (lane & 3) * 2 + r * 8;
    float v0 = W[k * F + n];
    float v1 = W[(k + 1) * F + n];
    uint32_t out = (hl == 0) ? pack_hi(v0, v1) : pack_lo(v0, v1);
    g_wfrag[layer][hl][kt][wn][lane][jr] = out;
}

// ---------------------------------------------------------------------------
// bf16x3 tensor-core GEMM via mma.sync:
//   out[M,128] = A[M,128] @ W[128,128] (fp32 in/out, fp32 accum)
// CTA: 64 rows. Warp grid 2x4, warp tile 32x32.
// Epilogue: outP = D ; outAcc = D*dinv[row]^2 + bias (self-loop + bias fused).
// ---------------------------------------------------------------------------
template <bool RELU_A>
__global__ void __launch_bounds__(256, 2)
k_gemm_mma(const float* __restrict__ A, const uint32_t* __restrict__ wfrag,
           const float* __restrict__ bias,
           float* __restrict__ outP, float* __restrict__ outAcc, int M)
{
    __shared__ __align__(16) __nv_bfloat16 Ah[64][136];
    __shared__ __align__(16) __nv_bfloat16 Al[64][136];

    const int tid  = threadIdx.x;
    const int wid  = tid >> 5;
    const int lane = tid & 31;
    const int wm = wid >> 2;     // 0..1
    const int wn = wid & 3;      // 0..3
    const int block_row = blockIdx.x * 64;

    // --- Fill A hi/lo tiles (split + optional ReLU on load) ---
    #pragma unroll
    for (int it = 0; it < 4; it++) {
        int seg = it * 256 + tid;          // 1024 segs: 64 rows x 16 (8-col segs)
        int r  = seg >> 4;
        int sk = (seg & 15) * 8;
        int grow = block_row + r;
        float4 a0 = make_float4(0.f,0.f,0.f,0.f), a1 = a0;
        if (grow < M) {
            a0 = *(const float4*)(A + (size_t)grow * F + sk);
            a1 = *(const float4*)(A + (size_t)grow * F + sk + 4);
        }
        if (RELU_A) {
            a0.x = fmaxf(a0.x,0.f); a0.y = fmaxf(a0.y,0.f); a0.z = fmaxf(a0.z,0.f); a0.w = fmaxf(a0.w,0.f);
            a1.x = fmaxf(a1.x,0.f); a1.y = fmaxf(a1.y,0.f); a1.z = fmaxf(a1.z,0.f); a1.w = fmaxf(a1.w,0.f);
        }
        uint4 hv = make_uint4(pack_hi(a0.x,a0.y), pack_hi(a0.z,a0.w),
                              pack_hi(a1.x,a1.y), pack_hi(a1.z,a1.w));
        uint4 lv = make_uint4(pack_lo(a0.x,a0.y), pack_lo(a0.z,a0.w),
                              pack_lo(a1.x,a1.y), pack_lo(a1.z,a1.w));
        *(uint4*)&Ah[r][sk] = hv;
        *(uint4*)&Al[r][sk] = lv;
    }
    __syncthreads();

    float acc[2][4][4];
    #pragma unroll
    for (int mt = 0; mt < 2; mt++)
        #pragma unroll
        for (int j = 0; j < 4; j++)
            #pragma unroll
            for (int q = 0; q < 4; q++) acc[mt][j][q] = 0.f;

    // ldmatrix per-lane addressing
    const int mat = lane >> 3, rr = lane & 7;
    const int lrow  = (mat & 1) * 8 + rr;
    const int lkoff = (mat >> 1) * 8;
    const uint32_t aBaseH = smem_u32(&Ah[0][0]);
    const uint32_t aBaseL = smem_u32(&Al[0][0]);

    #pragma unroll
    for (int ks = 0; ks < 8; ks++) {
        uint32_t ah[2][4], al[2][4];
        #pragma unroll
        for (int mt = 0; mt < 2; mt++) {
            uint32_t off = (uint32_t)(((wm * 32 + mt * 16 + lrow) * 136 + ks * 16 + lkoff) * 2);
            ldsm4(ah[mt], aBaseH + off);
            ldsm4(al[mt], aBaseL + off);
        }
        // B fragments: coalesced 2x uint4 per hi/lo
        const uint32_t* p_h = wfrag + (((size_t)(0 * 8 + ks) * 4 + wn) * 32 + lane) * 8;
        const uint32_t* p_l = wfrag + (((size_t)(1 * 8 + ks) * 4 + wn) * 32 + lane) * 8;
        uint4 h0 = *(const uint4*)p_h,       h1 = *(const uint4*)(p_h + 4);
        uint4 l0 = *(const uint4*)p_l,       l1 = *(const uint4*)(p_l + 4);
        uint32_t bh[8] = {h0.x,h0.y,h0.z,h0.w,h1.x,h1.y,h1.z,h1.w};
        uint32_t bl[8] = {l0.x,l0.y,l0.z,l0.w,l1.x,l1.y,l1.z,l1.w};

        #pragma unroll
        for (int mt = 0; mt < 2; mt++)
            #pragma unroll
            for (int j = 0; j < 4; j++) {
                mma_bf16(acc[mt][j], ah[mt], bh[2*j], bh[2*j+1]);
                mma_bf16(acc[mt][j], ah[mt], bl[2*j], bl[2*j+1]);
                mma_bf16(acc[mt][j], al[mt], bh[2*j], bh[2*j+1]);
            }
    }

    // --- Epilogue ---
    const int qrow = lane >> 2;
    const int qcol = (lane & 3) * 2;
    #pragma unroll
    for (int mt = 0; mt < 2; mt++) {
        int r0 = block_row + wm * 32 + mt * 16 + qrow;
        int r1 = r0 + 8;
        float s0 = 0.f, s1 = 0.f;
        if (r0 < M) { float d = g_dinv[r0]; s0 = d * d; }
        if (r1 < M) { float d = g_dinv[r1]; s1 = d * d; }
        #pragma unroll
        for (int j = 0; j < 4; j++) {
            int c = wn * 32 + j * 8 + qcol;
            float2 bb = *(const float2*)(bias + c);
            if (r0 < M) {
                float2 v = make_float2(acc[mt][j][0], acc[mt][j][1]);
                *(float2*)(outP + (size_t)r0 * F + c) = v;
                float2 w = make_float2(fmaf(v.x, s0, bb.x), fmaf(v.y, s0, bb.y));
                *(float2*)(outAcc + (size_t)r0 * F + c) = w;
            }
            if (r1 < M) {
                float2 v = make_float2(acc[mt][j][2], acc[mt][j][3]);
                *(float2*)(outP + (size_t)r1 * F + c) = v;
                float2 w = make_float2(fmaf(v.x, s1, bb.x), fmaf(v.y, s1, bb.y));
                *(float2*)(outAcc + (size_t)r1 * F + c) = w;
            }
        }
    }
}

// ---------------------------------------------------------------------------
// Edge aggregation: one warp per edge, vector red.global.add.v4.f32
// ---------------------------------------------------------------------------
__global__ void __launch_bounds__(256)
k_edge_agg(const float* __restrict__ src, const int* __restrict__ ei,
           float* __restrict__ acc, int E)
{
    int e = blockIdx.x * (blockDim.x >> 5) + (threadIdx.x >> 5);
    if (e >= E) return;
    int lane = threadIdx.x & 31;

    int r = __ldg(ei + e);
    int c = __ldg(ei + E + e);
    float norm = g_dinv[r] * g_dinv[c];

    float4 v = __ldg((const float4*)(src + (size_t)r * F) + lane);
    v.x *= norm; v.y *= norm; v.z *= norm; v.w *= norm;

    float* dst = acc + (size_t)c * F + lane * 4;
    asm volatile("red.global.add.v4.f32 [%0], {%1, %2, %3, %4};"
                 :: "l"(dst), "f"(v.x), "f"(v.y), "f"(v.z), "f"(v.w)
                 : "memory");
}

// ---------------------------------------------------------------------------
// Launch
// ---------------------------------------------------------------------------
extern "C" void kernel_launch(void* const* d_in, const int* in_sizes, int n_in,
                              void* d_out, int out_size)
{
    const float* x  = (const float*)d_in[0];
    const int*   ei = (const int*)d_in[1];
    const float* W1 = (const float*)d_in[2];
    const float* b1 = (const float*)d_in[3];
    const float* W2 = (const float*)d_in[4];
    const float* b2 = (const float*)d_in[5];
    float*       out = (float*)d_out;

    const int N = in_sizes[0] / F;   // 100000
    const int E = in_sizes[1] / 2;   // 640000

    float* xw;   cudaGetSymbolAddress((void**)&xw,   g_xw);
    float* acc1; cudaGetSymbolAddress((void**)&acc1, g_acc1);
    float* hw;   cudaGetSymbolAddress((void**)&hw,   g_hw);
    uint32_t* wfrag; cudaGetSymbolAddress((void**)&wfrag, g_wfrag);
    const size_t WFRAG_LAYER = 2ull * 8 * 4 * 32 * 8;  // u32 per layer

    const int T = 256;

    // Degree / normalization + W pre-split into fragment layout
    k_deg_init <<<(N + T - 1) / T, T>>>(N);
    k_deg_count<<<(E + T - 1) / T, T>>>(ei, E);
    k_dinv     <<<(N + T - 1) / T, T>>>(N);
    k_wsplit   <<<(16384 + T - 1) / T, T>>>(W1, 0);
    k_wsplit   <<<(16384 + T - 1) / T, T>>>(W2, 1);

    const int gemm_blocks = (N + 63) / 64;
    const int edge_blocks = (E + 7) / 8;

    // Layer 1
    k_gemm_mma<false><<<gemm_blocks, T>>>(x, wfrag, b1, xw, acc1, N);
    k_edge_agg<<<edge_blocks, T>>>(xw, ei, acc1, E);

    // Layer 2
    k_gemm_mma<true><<<gemm_blocks, T>>>(acc1, wfrag + WFRAG_LAYER, b2, hw, out, N);
    k_edge_agg<<<edge_blocks, T>>>(hw, ei, out, E);
}

// round 5
// speedup vs baseline: 2.2980x; 1.5363x over previous
#include <cuda_runtime.h>
#include <cuda_bf16.h>
#include <stdint.h>

#define NMAX 100000
#define EMAX 655360
#define F    128
#define NBMAX 512   // ceil(NMAX/256) = 391

// Scratch (allocation-free rule: __device__ globals)
__device__ float g_xw  [NMAX * F];
__device__ float g_acc1[NMAX * F];
__device__ float g_hw  [NMAX * F];
__device__ float g_deg [NMAX];
__device__ float g_dinv[NMAX];
// CSR by destination
__device__ int g_rowptr[NMAX + 1];
__device__ int g_cursor[NMAX];
__device__ int g_eidx  [EMAX];
__device__ int g_part  [NBMAX];
__device__ int g_boff  [NBMAX];
// W in mma B-fragment layout: [layer][hl][ktile(8)][warp_n(4)][lane(32)][8 u32]
__device__ uint32_t g_wfrag[2][2][8][4][32][8];

// ---------------------------------------------------------------------------
// Helpers
// ---------------------------------------------------------------------------
__device__ __forceinline__ uint32_t smem_u32(const void* p) {
    uint32_t a;
    asm("{ .reg .u64 t; cvta.to.shared.u64 t, %1; cvt.u32.u64 %0, t; }" : "=r"(a) : "l"(p));
    return a;
}
__device__ __forceinline__ uint32_t pack_hi(float a, float b) {
    __nv_bfloat16 x = __float2bfloat16_rn(a), y = __float2bfloat16_rn(b);
    return (uint32_t)*(unsigned short*)&x | ((uint32_t)*(unsigned short*)&y << 16);
}
__device__ __forceinline__ uint32_t pack_lo(float a, float b) {
    __nv_bfloat16 x = __float2bfloat16_rn(a), y = __float2bfloat16_rn(b);
    float ra = a - __bfloat162float(x), rb = b - __bfloat162float(y);
    __nv_bfloat16 lx = __float2bfloat16_rn(ra), ly = __float2bfloat16_rn(rb);
    return (uint32_t)*(unsigned short*)&lx | ((uint32_t)*(unsigned short*)&ly << 16);
}
__device__ __forceinline__ void mma_bf16(float* d, const uint32_t* a, uint32_t b0, uint32_t b1) {
    asm volatile(
        "mma.sync.aligned.m16n8k16.row.col.f32.bf16.bf16.f32 "
        "{%0,%1,%2,%3}, {%4,%5,%6,%7}, {%8,%9}, {%0,%1,%2,%3};"
        : "+f"(d[0]), "+f"(d[1]), "+f"(d[2]), "+f"(d[3])
        : "r"(a[0]), "r"(a[1]), "r"(a[2]), "r"(a[3]), "r"(b0), "r"(b1));
}
__device__ __forceinline__ void ldsm4(uint32_t* r, uint32_t addr) {
    asm volatile("ldmatrix.sync.aligned.m8n8.x4.shared.b16 {%0,%1,%2,%3}, [%4];"
                 : "=r"(r[0]), "=r"(r[1]), "=r"(r[2]), "=r"(r[3]) : "r"(addr));
}

// ---------------------------------------------------------------------------
// Degree / normalization
// ---------------------------------------------------------------------------
__global__ void k_deg_init(int N) {
    int i = blockIdx.x * blockDim.x + threadIdx.x;
    if (i < N) g_deg[i] = 1.0f;
}
__global__ void k_deg_count(const int* __restrict__ ei, int E) {
    int e = blockIdx.x * blockDim.x + threadIdx.x;
    if (e < E) atomicAdd(&g_deg[ei[E + e]], 1.0f);
}
__global__ void k_dinv(int N) {
    int i = blockIdx.x * blockDim.x + threadIdx.x;
    if (i < N) g_dinv[i] = rsqrtf(g_deg[i]);
}

// ---------------------------------------------------------------------------
// CSR build: cnt[i] = deg[i]-1 (in-degree sans self-loop); two-level scan.
// ---------------------------------------------------------------------------
__global__ void k_part(int N) {
    __shared__ int s[256];
    int i = blockIdx.x * 256 + threadIdx.x;
    int cnt = (i < N) ? ((int)g_deg[i] - 1) : 0;
    s[threadIdx.x] = cnt;
    __syncthreads();
    for (int off = 128; off > 0; off >>= 1) {
        if (threadIdx.x < off) s[threadIdx.x] += s[threadIdx.x + off];
        __syncthreads();
    }
    if (threadIdx.x == 0) g_part[blockIdx.x] = s[0];
}

__global__ void k_scan_part(int NB) {
    __shared__ int s[NBMAX];
    int i = threadIdx.x;
    int v = (i < NB) ? g_part[i] : 0;
    s[i] = v;
    __syncthreads();
    for (int off = 1; off < NBMAX; off <<= 1) {
        int t = (i >= off) ? s[i - off] : 0;
        __syncthreads();
        s[i] += t;
        __syncthreads();
    }
    if (i < NB) g_boff[i] = s[i] - v;
}

__global__ void k_rowptr(int N) {
    __shared__ int s[256];
    int i = blockIdx.x * 256 + threadIdx.x;
    int cnt = (i < N) ? ((int)g_deg[i] - 1) : 0;
    s[threadIdx.x] = cnt;
    __syncthreads();
    for (int off = 1; off < 256; off <<= 1) {
        int t = (threadIdx.x >= off) ? s[threadIdx.x - off] : 0;
        __syncthreads();
        s[threadIdx.x] += t;
        __syncthreads();
    }
    int incl = s[threadIdx.x];
    int base = g_boff[blockIdx.x];
    if (i < N) {
        int rp = base + incl - cnt;
        g_rowptr[i] = rp;
        g_cursor[i] = rp;
        if (i == N - 1) g_rowptr[N] = base + incl;
    }
}

__global__ void k_scatter(const int* __restrict__ ei, int E) {
    int e = blockIdx.x * blockDim.x + threadIdx.x;
    if (e < E) {
        int r = ei[e];
        int c = ei[E + e];
        int pos = atomicAdd(&g_cursor[c], 1);
        g_eidx[pos] = r;
    }
}

// ---------------------------------------------------------------------------
// W split into mma B-fragment layout (hi/lo bf16).
// ---------------------------------------------------------------------------
__global__ void k_wsplit(const float* __restrict__ W, int layer) {
    int id = blockIdx.x * blockDim.x + threadIdx.x;
    if (id >= 16384) return;
    int jr   = id & 7;
    int lane = (id >> 3) & 31;
    int wn   = (id >> 8) & 3;
    int kt   = (id >> 10) & 7;
    int hl   = id >> 13;
    int j = jr >> 1, r = jr & 1;
    int n = (wn * 4 + j) * 8 + (lane >> 2);
    int k = kt * 16 + (lane & 3) * 2 + r * 8;
    float v0 = W[k * F + n];
    float v1 = W[(k + 1) * F + n];
    uint32_t out = (hl == 0) ? pack_hi(v0, v1) : pack_lo(v0, v1);
    g_wfrag[layer][hl][kt][wn][lane][jr] = out;
}

// ---------------------------------------------------------------------------
// bf16x3 tensor-core GEMM via mma.sync: outP[M,128] = A[M,128] @ W[128,128]
// CTA: 64 rows, warp grid 2x4, warp tile 32x32.
// ---------------------------------------------------------------------------
template <bool RELU_A>
__global__ void __launch_bounds__(256, 2)
k_gemm_mma(const float* __restrict__ A, const uint32_t* __restrict__ wfrag,
           float* __restrict__ outP, int M)
{
    __shared__ __align__(16) __nv_bfloat16 Ah[64][136];
    __shared__ __align__(16) __nv_bfloat16 Al[64][136];

    const int tid  = threadIdx.x;
    const int wid  = tid >> 5;
    const int lane = tid & 31;
    const int wm = wid >> 2;
    const int wn = wid & 3;
    const int block_row = blockIdx.x * 64;

    #pragma unroll
    for (int it = 0; it < 4; it++) {
        int seg = it * 256 + tid;
        int r  = seg >> 4;
        int sk = (seg & 15) * 8;
        int grow = block_row + r;
        float4 a0 = make_float4(0.f,0.f,0.f,0.f), a1 = a0;
        if (grow < M) {
            a0 = *(const float4*)(A + (size_t)grow * F + sk);
            a1 = *(const float4*)(A + (size_t)grow * F + sk + 4);
        }
        if (RELU_A) {
            a0.x = fmaxf(a0.x,0.f); a0.y = fmaxf(a0.y,0.f); a0.z = fmaxf(a0.z,0.f); a0.w = fmaxf(a0.w,0.f);
            a1.x = fmaxf(a1.x,0.f); a1.y = fmaxf(a1.y,0.f); a1.z = fmaxf(a1.z,0.f); a1.w = fmaxf(a1.w,0.f);
        }
        uint4 hv = make_uint4(pack_hi(a0.x,a0.y), pack_hi(a0.z,a0.w),
                              pack_hi(a1.x,a1.y), pack_hi(a1.z,a1.w));
        uint4 lv = make_uint4(pack_lo(a0.x,a0.y), pack_lo(a0.z,a0.w),
                              pack_lo(a1.x,a1.y), pack_lo(a1.z,a1.w));
        *(uint4*)&Ah[r][sk] = hv;
        *(uint4*)&Al[r][sk] = lv;
    }
    __syncthreads();

    float acc[2][4][4];
    #pragma unroll
    for (int mt = 0; mt < 2; mt++)
        #pragma unroll
        for (int j = 0; j < 4; j++)
            #pragma unroll
            for (int q = 0; q < 4; q++) acc[mt][j][q] = 0.f;

    const int mat = lane >> 3, rr = lane & 7;
    const int lrow  = (mat & 1) * 8 + rr;
    const int lkoff = (mat >> 1) * 8;
    const uint32_t aBaseH = smem_u32(&Ah[0][0]);
    const uint32_t aBaseL = smem_u32(&Al[0][0]);

    #pragma unroll
    for (int ks = 0; ks < 8; ks++) {
        uint32_t ah[2][4], al[2][4];
        #pragma unroll
        for (int mt = 0; mt < 2; mt++) {
            uint32_t off = (uint32_t)(((wm * 32 + mt * 16 + lrow) * 136 + ks * 16 + lkoff) * 2);
            ldsm4(ah[mt], aBaseH + off);
            ldsm4(al[mt], aBaseL + off);
        }
        const uint32_t* p_h = wfrag + (((size_t)(0 * 8 + ks) * 4 + wn) * 32 + lane) * 8;
        const uint32_t* p_l = wfrag + (((size_t)(1 * 8 + ks) * 4 + wn) * 32 + lane) * 8;
        uint4 h0 = *(const uint4*)p_h, h1 = *(const uint4*)(p_h + 4);
        uint4 l0 = *(const uint4*)p_l, l1 = *(const uint4*)(p_l + 4);
        uint32_t bh[8] = {h0.x,h0.y,h0.z,h0.w,h1.x,h1.y,h1.z,h1.w};
        uint32_t bl[8] = {l0.x,l0.y,l0.z,l0.w,l1.x,l1.y,l1.z,l1.w};

        #pragma unroll
        for (int mt = 0; mt < 2; mt++)
            #pragma unroll
            for (int j = 0; j < 4; j++) {
                mma_bf16(acc[mt][j], ah[mt], bh[2*j], bh[2*j+1]);
                mma_bf16(acc[mt][j], ah[mt], bl[2*j], bl[2*j+1]);
                mma_bf16(acc[mt][j], al[mt], bh[2*j], bh[2*j+1]);
            }
    }

    const int qrow = lane >> 2;
    const int qcol = (lane & 3) * 2;
    #pragma unroll
    for (int mt = 0; mt < 2; mt++) {
        int r0 = block_row + wm * 32 + mt * 16 + qrow;
        int r1 = r0 + 8;
        #pragma unroll
        for (int j = 0; j < 4; j++) {
            int c = wn * 32 + j * 8 + qcol;
            if (r0 < M) *(float2*)(outP + (size_t)r0 * F + c) = make_float2(acc[mt][j][0], acc[mt][j][1]);
            if (r1 < M) *(float2*)(outP + (size_t)r1 * F + c) = make_float2(acc[mt][j][2], acc[mt][j][3]);
        }
    }
}

// ---------------------------------------------------------------------------
// CSR gather aggregation: one warp per destination node.
//   dst[c] = bias + dinv[c]^2 * src[c] + sum_{r in in(c)} dinv[c]*dinv[r]*src[r]
// No atomics; register accumulators; 32 lanes x float4 = 128 cols.
// ---------------------------------------------------------------------------
__global__ void __launch_bounds__(256)
k_agg_csr(const float* __restrict__ src, const float* __restrict__ bias,
          float* __restrict__ dst, int N)
{
    int node = blockIdx.x * (blockDim.x >> 5) + (threadIdx.x >> 5);
    if (node >= N) return;
    int lane = threadIdx.x & 31;

    float dc = g_dinv[node];
    float s  = dc * dc;

    float4 acc = __ldg((const float4*)(src + (size_t)node * F) + lane);
    float4 bb  = __ldg((const float4*)bias + lane);
    acc.x = fmaf(acc.x, s, bb.x);
    acc.y = fmaf(acc.y, s, bb.y);
    acc.z = fmaf(acc.z, s, bb.z);
    acc.w = fmaf(acc.w, s, bb.w);

    int start = g_rowptr[node];
    int end   = g_rowptr[node + 1];

    for (int base = start; base < end; base += 32) {
        int id = 0;
        if (base + lane < end) id = __ldg(&g_eidx[base + lane]);
        int cnt = min(end - base, 32);
        #pragma unroll 4
        for (int j = 0; j < cnt; j++) {
            int r = __shfl_sync(0xffffffff, id, j);
            float w = dc * g_dinv[r];
            float4 v = __ldg((const float4*)(src + (size_t)r * F) + lane);
            acc.x = fmaf(v.x, w, acc.x);
            acc.y = fmaf(v.y, w, acc.y);
            acc.z = fmaf(v.z, w, acc.z);
            acc.w = fmaf(v.w, w, acc.w);
        }
    }

    *((float4*)(dst + (size_t)node * F) + lane) = acc;
}

// ---------------------------------------------------------------------------
// Launch
// ---------------------------------------------------------------------------
extern "C" void kernel_launch(void* const* d_in, const int* in_sizes, int n_in,
                              void* d_out, int out_size)
{
    const float* x  = (const float*)d_in[0];
    const int*   ei = (const int*)d_in[1];
    const float* W1 = (const float*)d_in[2];
    const float* b1 = (const float*)d_in[3];
    const float* W2 = (const float*)d_in[4];
    const float* b2 = (const float*)d_in[5];
    float*       out = (float*)d_out;

    const int N = in_sizes[0] / F;   // 100000
    const int E = in_sizes[1] / 2;   // 640000

    float* xw;   cudaGetSymbolAddress((void**)&xw,   g_xw);
    float* acc1; cudaGetSymbolAddress((void**)&acc1, g_acc1);
    float* hw;   cudaGetSymbolAddress((void**)&hw,   g_hw);
    uint32_t* wfrag; cudaGetSymbolAddress((void**)&wfrag, g_wfrag);
    const size_t WFRAG_LAYER = 2ull * 8 * 4 * 32 * 8;

    const int T  = 256;
    const int NB = (N + 255) / 256;

    // Degree / normalization
    k_deg_init <<<(N + T - 1) / T, T>>>(N);
    k_deg_count<<<(E + T - 1) / T, T>>>(ei, E);
    k_dinv     <<<(N + T - 1) / T, T>>>(N);

    // CSR build (edge structure shared by both layers)
    k_part     <<<NB, 256>>>(N);
    k_scan_part<<<1, NBMAX>>>(NB);
    k_rowptr   <<<NB, 256>>>(N);
    k_scatter  <<<(E + T - 1) / T, T>>>(ei, E);

    // W pre-split into fragment layout
    k_wsplit<<<(16384 + T - 1) / T, T>>>(W1, 0);
    k_wsplit<<<(16384 + T - 1) / T, T>>>(W2, 1);

    const int gemm_blocks = (N + 63) / 64;
    const int agg_blocks  = (N + 7) / 8;   // 8 warps (nodes) per block

    // Layer 1
    k_gemm_mma<false><<<gemm_blocks, T>>>(x, wfrag, xw, N);
    k_agg_csr<<<agg_blocks, T>>>(xw, b1, acc1, N);

    // Layer 2
    k_gemm_mma<true><<<gemm_blocks, T>>>(acc1, wfrag + WFRAG_LAYER, hw, N);
    k_agg_csr<<<agg_blocks, T>>>(hw, b2, out, N);
}

// round 6
// speedup vs baseline: 2.3495x; 1.0224x over previous
#include <cuda_runtime.h>
#include <cuda_bf16.h>
#include <stdint.h>

#define NMAX   100000
#define F      128
#define DCAP   64          // bucket capacity per node (P(deg>64) ~ 0)
#define OVFMAX 4096        // overflow-edge safety list

// Scratch (allocation-free rule: __device__ globals)
__device__ float g_xw  [NMAX * F];
__device__ float g_acc1[NMAX * F];
__device__ float g_hw  [NMAX * F];
__device__ int   g_cursor[NMAX + 1];      // [N] = overflow counter
__device__ int   g_eidx[NMAX * DCAP];     // per-dst neighbor buckets
__device__ int   g_ovf [2 * OVFMAX];      // (r,c) pairs that overflowed
// W in mma B-fragment layout: [layer][hl][ktile(8)][warp_n(4)][lane(32)][8 u32]
__device__ uint32_t g_wfrag[2][2][8][4][32][8];

// ---------------------------------------------------------------------------
// Helpers
// ---------------------------------------------------------------------------
__device__ __forceinline__ uint32_t smem_u32(const void* p) {
    uint32_t a;
    asm("{ .reg .u64 t; cvta.to.shared.u64 t, %1; cvt.u32.u64 %0, t; }" : "=r"(a) : "l"(p));
    return a;
}
__device__ __forceinline__ uint32_t pack_hi(float a, float b) {
    __nv_bfloat16 x = __float2bfloat16_rn(a), y = __float2bfloat16_rn(b);
    return (uint32_t)*(unsigned short*)&x | ((uint32_t)*(unsigned short*)&y << 16);
}
__device__ __forceinline__ uint32_t pack_lo(float a, float b) {
    __nv_bfloat16 x = __float2bfloat16_rn(a), y = __float2bfloat16_rn(b);
    float ra = a - __bfloat162float(x), rb = b - __bfloat162float(y);
    __nv_bfloat16 lx = __float2bfloat16_rn(ra), ly = __float2bfloat16_rn(rb);
    return (uint32_t)*(unsigned short*)&lx | ((uint32_t)*(unsigned short*)&ly << 16);
}
__device__ __forceinline__ void mma_bf16(float* d, const uint32_t* a, uint32_t b0, uint32_t b1) {
    asm volatile(
        "mma.sync.aligned.m16n8k16.row.col.f32.bf16.bf16.f32 "
        "{%0,%1,%2,%3}, {%4,%5,%6,%7}, {%8,%9}, {%0,%1,%2,%3};"
        : "+f"(d[0]), "+f"(d[1]), "+f"(d[2]), "+f"(d[3])
        : "r"(a[0]), "r"(a[1]), "r"(a[2]), "r"(a[3]), "r"(b0), "r"(b1));
}
__device__ __forceinline__ void ldsm4(uint32_t* r, uint32_t addr) {
    asm volatile("ldmatrix.sync.aligned.m8n8.x4.shared.b16 {%0,%1,%2,%3}, [%4];"
                 : "=r"(r[0]), "=r"(r[1]), "=r"(r[2]), "=r"(r[3]) : "r"(addr));
}

// ---------------------------------------------------------------------------
// W split into mma B-fragment layout (hi/lo bf16) — both layers, one launch.
// ---------------------------------------------------------------------------
__global__ void k_wsplit(const float* __restrict__ W1, const float* __restrict__ W2) {
    int id = blockIdx.x * blockDim.x + threadIdx.x;   // 32768 total
    if (id >= 2 * 16384) return;
    int layer = id >> 14;
    int v     = id & 16383;
    int jr   = v & 7;
    int lane = (v >> 3) & 31;
    int wn   = (v >> 8) & 3;
    int kt   = (v >> 10) & 7;
    int hl   = v >> 13;
    int j = jr >> 1, r = jr & 1;
    int n = (wn * 4 + j) * 8 + (lane >> 2);
    int k = kt * 16 + (lane & 3) * 2 + r * 8;
    const float* W = layer ? W2 : W1;
    float v0 = W[k * F + n];
    float v1 = W[(k + 1) * F + n];
    g_wfrag[layer][hl][kt][wn][lane][jr] = (hl == 0) ? pack_hi(v0, v1) : pack_lo(v0, v1);
}

// ---------------------------------------------------------------------------
// bf16x3 GEMM block body (device function, shared by plain + mega kernels)
// ---------------------------------------------------------------------------
template <bool RELU_A>
__device__ __forceinline__ void gemm_block(
    const float* __restrict__ A, const uint32_t* __restrict__ wfrag,
    float* __restrict__ outP, int M, int bb)
{
    __shared__ __align__(16) __nv_bfloat16 Ah[64][136];
    __shared__ __align__(16) __nv_bfloat16 Al[64][136];

    const int tid  = threadIdx.x;
    const int wid  = tid >> 5;
    const int lane = tid & 31;
    const int wm = wid >> 2;
    const int wn = wid & 3;
    const int block_row = bb * 64;

    #pragma unroll
    for (int it = 0; it < 4; it++) {
        int seg = it * 256 + tid;
        int r  = seg >> 4;
        int sk = (seg & 15) * 8;
        int grow = block_row + r;
        float4 a0 = make_float4(0.f,0.f,0.f,0.f), a1 = a0;
        if (grow < M) {
            a0 = *(const float4*)(A + (size_t)grow * F + sk);
            a1 = *(const float4*)(A + (size_t)grow * F + sk + 4);
        }
        if (RELU_A) {
            a0.x = fmaxf(a0.x,0.f); a0.y = fmaxf(a0.y,0.f); a0.z = fmaxf(a0.z,0.f); a0.w = fmaxf(a0.w,0.f);
            a1.x = fmaxf(a1.x,0.f); a1.y = fmaxf(a1.y,0.f); a1.z = fmaxf(a1.z,0.f); a1.w = fmaxf(a1.w,0.f);
        }
        *(uint4*)&Ah[r][sk] = make_uint4(pack_hi(a0.x,a0.y), pack_hi(a0.z,a0.w),
                                         pack_hi(a1.x,a1.y), pack_hi(a1.z,a1.w));
        *(uint4*)&Al[r][sk] = make_uint4(pack_lo(a0.x,a0.y), pack_lo(a0.z,a0.w),
                                         pack_lo(a1.x,a1.y), pack_lo(a1.z,a1.w));
    }
    __syncthreads();

    float acc[2][4][4];
    #pragma unroll
    for (int mt = 0; mt < 2; mt++)
        #pragma unroll
        for (int j = 0; j < 4; j++)
            #pragma unroll
            for (int q = 0; q < 4; q++) acc[mt][j][q] = 0.f;

    const int mat = lane >> 3, rr = lane & 7;
    const int lrow  = (mat & 1) * 8 + rr;
    const int lkoff = (mat >> 1) * 8;
    const uint32_t aBaseH = smem_u32(&Ah[0][0]);
    const uint32_t aBaseL = smem_u32(&Al[0][0]);

    #pragma unroll
    for (int ks = 0; ks < 8; ks++) {
        uint32_t ah[2][4], al[2][4];
        #pragma unroll
        for (int mt = 0; mt < 2; mt++) {
            uint32_t off = (uint32_t)(((wm * 32 + mt * 16 + lrow) * 136 + ks * 16 + lkoff) * 2);
            ldsm4(ah[mt], aBaseH + off);
            ldsm4(al[mt], aBaseL + off);
        }
        const uint32_t* p_h = wfrag + (((size_t)(0 * 8 + ks) * 4 + wn) * 32 + lane) * 8;
        const uint32_t* p_l = wfrag + (((size_t)(1 * 8 + ks) * 4 + wn) * 32 + lane) * 8;
        uint4 h0 = *(const uint4*)p_h, h1 = *(const uint4*)(p_h + 4);
        uint4 l0 = *(const uint4*)p_l, l1 = *(const uint4*)(p_l + 4);
        uint32_t bh[8] = {h0.x,h0.y,h0.z,h0.w,h1.x,h1.y,h1.z,h1.w};
        uint32_t bl[8] = {l0.x,l0.y,l0.z,l0.w,l1.x,l1.y,l1.z,l1.w};

        #pragma unroll
        for (int mt = 0; mt < 2; mt++)
            #pragma unroll
            for (int j = 0; j < 4; j++) {
                mma_bf16(acc[mt][j], ah[mt], bh[2*j], bh[2*j+1]);
                mma_bf16(acc[mt][j], ah[mt], bl[2*j], bl[2*j+1]);
                mma_bf16(acc[mt][j], al[mt], bh[2*j], bh[2*j+1]);
            }
    }

    const int qrow = lane >> 2;
    const int qcol = (lane & 3) * 2;
    #pragma unroll
    for (int mt = 0; mt < 2; mt++) {
        int r0 = block_row + wm * 32 + mt * 16 + qrow;
        int r1 = r0 + 8;
        #pragma unroll
        for (int j = 0; j < 4; j++) {
            int c = wn * 32 + j * 8 + qcol;
            if (r0 < M) *(float2*)(outP + (size_t)r0 * F + c) = make_float2(acc[mt][j][0], acc[mt][j][1]);
            if (r1 < M) *(float2*)(outP + (size_t)r1 * F + c) = make_float2(acc[mt][j][2], acc[mt][j][3]);
        }
    }
}

// ---------------------------------------------------------------------------
// Mega kernel 1: GEMM layer-1 blocks + edge-scatter blocks (independent work)
// ---------------------------------------------------------------------------
__global__ void __launch_bounds__(256, 2)
k_mega1(const float* __restrict__ A, const uint32_t* __restrict__ wfrag,
        float* __restrict__ outP, const int* __restrict__ ei,
        int M, int E, int gemm_blocks)
{
    if ((int)blockIdx.x < gemm_blocks) {
        gemm_block<false>(A, wfrag, outP, M, blockIdx.x);
        return;
    }
    // scatter: bucket edges by destination
    int e = (blockIdx.x - gemm_blocks) * 256 + threadIdx.x;
    if (e < E) {
        int r = __ldg(ei + e);
        int c = __ldg(ei + E + e);
        int pos = atomicAdd(&g_cursor[c], 1);
        if (pos < DCAP) {
            g_eidx[c * DCAP + pos] = r;
        } else {
            int o = atomicAdd(&g_cursor[NMAX], 1);
            if (o < OVFMAX) { g_ovf[2 * o] = r; g_ovf[2 * o + 1] = c; }
        }
    }
}

// Plain GEMM (layer 2)
template <bool RELU_A>
__global__ void __launch_bounds__(256, 2)
k_gemm_mma(const float* __restrict__ A, const uint32_t* __restrict__ wfrag,
           float* __restrict__ outP, int M)
{
    gemm_block<RELU_A>(A, wfrag, outP, M, blockIdx.x);
}

// ---------------------------------------------------------------------------
// Bucket-gather aggregation: one warp per destination node.
//   dinv computed on the fly: dinv[i] = rsqrt(cursor[i] + 1)
// ---------------------------------------------------------------------------
__global__ void __launch_bounds__(256)
k_agg(const float* __restrict__ src, const float* __restrict__ bias,
      float* __restrict__ dst, int N)
{
    int node = blockIdx.x * (blockDim.x >> 5) + (threadIdx.x >> 5);
    if (node >= N) return;
    int lane = threadIdx.x & 31;

    int cr = __ldg(&g_cursor[node]);
    float dc = rsqrtf((float)(cr + 1));
    float s  = dc * dc;

    float4 acc = __ldg((const float4*)(src + (size_t)node * F) + lane);
    float4 bb  = __ldg((const float4*)bias + lane);
    acc.x = fmaf(acc.x, s, bb.x);
    acc.y = fmaf(acc.y, s, bb.y);
    acc.z = fmaf(acc.z, s, bb.z);
    acc.w = fmaf(acc.w, s, bb.w);

    int cnt = min(cr, DCAP);
    const int* bucket = g_eidx + node * DCAP;

    for (int base = 0; base < cnt; base += 32) {
        int id = 0;
        if (base + lane < cnt) id = __ldg(bucket + base + lane);
        int m = min(cnt - base, 32);
        #pragma unroll 4
        for (int j = 0; j < m; j++) {
            int r = __shfl_sync(0xffffffff, id, j);
            float dr = rsqrtf((float)(__ldg(&g_cursor[r]) + 1));
            float w = dc * dr;
            float4 v = __ldg((const float4*)(src + (size_t)r * F) + lane);
            acc.x = fmaf(v.x, w, acc.x);
            acc.y = fmaf(v.y, w, acc.y);
            acc.z = fmaf(v.z, w, acc.z);
            acc.w = fmaf(v.w, w, acc.w);
        }
    }

    *((float4*)(dst + (size_t)node * F) + lane) = acc;
}

// ---------------------------------------------------------------------------
// Overflow fixup (virtually never does work; correctness insurance)
// ---------------------------------------------------------------------------
__global__ void __launch_bounds__(256)
k_ovf(const float* __restrict__ src, float* __restrict__ dst)
{
    int cnt = min(g_cursor[NMAX], OVFMAX);
    if (cnt == 0) return;
    int lane = threadIdx.x & 31;
    int w0 = blockIdx.x * (blockDim.x >> 5) + (threadIdx.x >> 5);
    int stride = gridDim.x * (blockDim.x >> 5);
    for (int e = w0; e < cnt; e += stride) {
        int r = g_ovf[2 * e], c = g_ovf[2 * e + 1];
        float w = rsqrtf((float)(g_cursor[r] + 1)) * rsqrtf((float)(g_cursor[c] + 1));
        float4 v = __ldg((const float4*)(src + (size_t)r * F) + lane);
        v.x *= w; v.y *= w; v.z *= w; v.w *= w;
        float* d = dst + (size_t)c * F + lane * 4;
        asm volatile("red.global.add.v4.f32 [%0], {%1, %2, %3, %4};"
                     :: "l"(d), "f"(v.x), "f"(v.y), "f"(v.z), "f"(v.w) : "memory");
    }
}

// ---------------------------------------------------------------------------
// Launch
// ---------------------------------------------------------------------------
extern "C" void kernel_launch(void* const* d_in, const int* in_sizes, int n_in,
                              void* d_out, int out_size)
{
    const float* x  = (const float*)d_in[0];
    const int*   ei = (const int*)d_in[1];
    const float* W1 = (const float*)d_in[2];
    const float* b1 = (const float*)d_in[3];
    const float* W2 = (const float*)d_in[4];
    const float* b2 = (const float*)d_in[5];
    float*       out = (float*)d_out;

    const int N = in_sizes[0] / F;   // 100000
    const int E = in_sizes[1] / 2;   // 640000

    float* xw;   cudaGetSymbolAddress((void**)&xw,   g_xw);
    float* acc1; cudaGetSymbolAddress((void**)&acc1, g_acc1);
    float* hw;   cudaGetSymbolAddress((void**)&hw,   g_hw);
    int* cursor; cudaGetSymbolAddress((void**)&cursor, g_cursor);
    uint32_t* wfrag; cudaGetSymbolAddress((void**)&wfrag, g_wfrag);
    const size_t WFRAG_LAYER = 2ull * 8 * 4 * 32 * 8;

    const int gemm_blocks = (N + 63) / 64;
    const int scat_blocks = (E + 255) / 256;
    const int agg_blocks  = (N + 7) / 8;

    // Zero bucket cursors + overflow counter
    cudaMemsetAsync(cursor, 0, (NMAX + 1) * sizeof(int));

    // W pre-split (both layers, one launch)
    k_wsplit<<<128, 256>>>(W1, W2);

    // GEMM1 + edge scatter fused
    k_mega1<<<gemm_blocks + scat_blocks, 256>>>(x, wfrag, xw, ei, N, E, gemm_blocks);

    // Layer 1 aggregation (+ overflow fixup)
    k_agg<<<agg_blocks, 256>>>(xw, b1, acc1, N);
    k_ovf<<<8, 256>>>(xw, acc1);

    // Layer 2
    k_gemm_mma<true><<<gemm_blocks, 256>>>(acc1, wfrag + WFRAG_LAYER, hw, N);
    k_agg<<<agg_blocks, 256>>>(hw, b2, out, N);
    k_ovf<<<8, 256>>>(hw, out);
}